// round 5
// baseline (speedup 1.0000x reference)
#include <cuda_runtime.h>

#define NN 50000      // nodes
#define NE 50000      // hyperedges
#define EE 320000     // incidences
#define DD 256        // feature dim

// ---------------- scratch (device globals; no allocation allowed) -------------
__device__ float g_xw[NN * DD];      // X @ W^T
__device__ float g_edge[NE * DD];    // hyperedge features
__device__ float g_h1[NN * DD];      // layer-1 output
__device__ int g_deg_n[NN];
__device__ int g_deg_e[NE];
__device__ int g_he_ptr[NE + 1];     // CSR by hyperedge -> node slots
__device__ int g_node_ptr[NN + 1];   // CSR by node -> hyperedge slots
__device__ int g_cur_he[NE];
__device__ int g_cur_node[NN];
__device__ int g_he_slots[EE];
__device__ int g_node_slots[EE];
__device__ int g_is_i32;

// ---------------- helpers ------------------------------------------------------
__device__ __forceinline__ int ld_idx(const void* p, long long e, int is32) {
    if (is32) return ((const int*)p)[e];
    return (int)(((const long long*)p)[e]);
}

// ---------------- init / dtype detect ------------------------------------------
__global__ void init_k() {
    int i = blockIdx.x * blockDim.x + threadIdx.x;
    if (i < NN) { g_deg_n[i] = 0; g_deg_e[i] = 0; }
    if (i == 0) g_is_i32 = 0;
}

// Genuine int64 indices are all < 50000. If the buffer actually holds int32,
// each u64 word packs two values and is >= 2^32 unless the high int32 is 0
// (prob 1/50000 per word). 1024 words make misdetection impossible in practice.
__global__ void detect_k(const unsigned long long* __restrict__ p) {
    unsigned long long v = p[threadIdx.x];
    unsigned int bad = __ballot_sync(0xffffffffu, v > 49999ULL);
    if ((threadIdx.x & 31) == 0 && bad) atomicOr(&g_is_i32, 1);
}

// ---------------- degree histogram ----------------------------------------------
__global__ void hist_k(const void* __restrict__ hei) {
    int e = blockIdx.x * blockDim.x + threadIdx.x;
    if (e >= EE) return;
    int f = g_is_i32;
    int s = ld_idx(hei, e, f);        // row 0: node index
    int h = ld_idx(hei, EE + e, f);   // row 1: hyperedge index
    atomicAdd(&g_deg_n[s], 1);
    atomicAdd(&g_deg_e[h], 1);
}

// ---------------- single-block exclusive scan (n = 50000) -----------------------
__global__ void scan_k(int which) {
    const int* __restrict__ in = which ? g_deg_n : g_deg_e;
    int* __restrict__ out = which ? g_node_ptr : g_he_ptr;
    const int n = NN;  // == NE
    __shared__ int part[1024];
    int tid = threadIdx.x;
    int chunk = (n + 1023) >> 10;
    int lo = tid * chunk;
    int hi = min(lo + chunk, n);
    int s = 0;
    for (int i = lo; i < hi; i++) s += in[i];
    part[tid] = s;
    __syncthreads();
    for (int off = 1; off < 1024; off <<= 1) {
        int t = (tid >= off) ? part[tid - off] : 0;
        __syncthreads();
        part[tid] += t;
        __syncthreads();
    }
    int run = (tid == 0) ? 0 : part[tid - 1];
    for (int i = lo; i < hi; i++) { out[i] = run; run += in[i]; }
    if (tid == 1023) out[n] = run;
}

__global__ void cursor_k() {
    int i = blockIdx.x * blockDim.x + threadIdx.x;
    if (i < NN) { g_cur_he[i] = g_he_ptr[i]; g_cur_node[i] = g_node_ptr[i]; }
}

__global__ void fill_k(const void* __restrict__ hei) {
    int e = blockIdx.x * blockDim.x + threadIdx.x;
    if (e >= EE) return;
    int f = g_is_i32;
    int s = ld_idx(hei, e, f);
    int h = ld_idx(hei, EE + e, f);
    g_he_slots[atomicAdd(&g_cur_he[h], 1)] = s;
    g_node_slots[atomicAdd(&g_cur_node[s], 1)] = h;
}

// ---------------- SGEMM: C[m][n] = sum_k A[m][k] * W[n][k]  (C = A @ W^T) -------
// 128x128 tile, BK=16, 256 threads, 8x8 per-thread microtile.
__global__ __launch_bounds__(256, 2) void gemm_k(const float* __restrict__ Aext,
                                                 const float* __restrict__ W,
                                                 int useH1) {
    const float* __restrict__ A = useH1 ? (const float*)g_h1 : Aext;
    float* __restrict__ C = g_xw;
    const int M = NN;

    __shared__ float As[16][128];
    __shared__ float Bs[16][128];

    int bm = blockIdx.x * 128;
    int bn = blockIdx.y * 128;
    int tid = threadIdx.x;
    int tx = tid & 15;   // -> 8 cols
    int ty = tid >> 4;   // -> 8 rows

    float acc[8][8];
#pragma unroll
    for (int i = 0; i < 8; i++)
#pragma unroll
        for (int j = 0; j < 8; j++) acc[i][j] = 0.f;

    for (int kb = 0; kb < DD; kb += 16) {
#pragma unroll
        for (int jj = 0; jj < 2; jj++) {
            int f  = tid + jj * 256;     // float4 index 0..511
            int r  = f >> 2;             // tile row 0..127
            int c4 = (f & 3) << 2;       // k offset 0,4,8,12
            int grow = bm + r;
            float4 v = make_float4(0.f, 0.f, 0.f, 0.f);
            if (grow < M) v = *(const float4*)&A[(size_t)grow * DD + kb + c4];
            As[c4 + 0][r] = v.x; As[c4 + 1][r] = v.y;
            As[c4 + 2][r] = v.z; As[c4 + 3][r] = v.w;
            float4 w = *(const float4*)&W[(size_t)(bn + r) * DD + kb + c4];
            Bs[c4 + 0][r] = w.x; Bs[c4 + 1][r] = w.y;
            Bs[c4 + 2][r] = w.z; Bs[c4 + 3][r] = w.w;
        }
        __syncthreads();
#pragma unroll
        for (int k = 0; k < 16; k++) {
            float ra[8], rb[8];
#pragma unroll
            for (int i = 0; i < 8; i++) ra[i] = As[k][ty * 8 + i];
#pragma unroll
            for (int j = 0; j < 8; j++) rb[j] = Bs[k][tx * 8 + j];
#pragma unroll
            for (int i = 0; i < 8; i++)
#pragma unroll
                for (int j = 0; j < 8; j++)
                    acc[i][j] += ra[i] * rb[j];
        }
        __syncthreads();
    }

#pragma unroll
    for (int i = 0; i < 8; i++) {
        int grow = bm + ty * 8 + i;
        if (grow < M) {
#pragma unroll
            for (int j = 0; j < 8; j += 4) {
                float4 v = make_float4(acc[i][j], acc[i][j + 1],
                                       acc[i][j + 2], acc[i][j + 3]);
                *(float4*)&C[(size_t)grow * DD + bn + tx * 8 + j] = v;
            }
        }
    }
}

// ---------------- aggregation: hyperedge <- mean over incident nodes ------------
// one warp per hyperedge row; lane covers 8 floats (2 x float4)
__global__ void edge_agg_k() {
    int gw = (blockIdx.x * blockDim.x + threadIdx.x) >> 5;
    int lane = threadIdx.x & 31;
    if (gw >= NE) return;
    int lo = g_he_ptr[gw], hi = g_he_ptr[gw + 1];
    float4 a0 = make_float4(0.f, 0.f, 0.f, 0.f);
    float4 a1 = a0;
    for (int s = lo; s < hi; s++) {
        int n = g_he_slots[s];
        const float4* row = (const float4*)(g_xw + (size_t)n * DD);
        float4 v0 = __ldg(&row[lane]);
        float4 v1 = __ldg(&row[lane + 32]);
        a0.x += v0.x; a0.y += v0.y; a0.z += v0.z; a0.w += v0.w;
        a1.x += v1.x; a1.y += v1.y; a1.z += v1.z; a1.w += v1.w;
    }
    float inv = (hi > lo) ? 1.f / (float)(hi - lo) : 0.f;
    a0.x *= inv; a0.y *= inv; a0.z *= inv; a0.w *= inv;
    a1.x *= inv; a1.y *= inv; a1.z *= inv; a1.w *= inv;
    float4* orow = (float4*)(g_edge + (size_t)gw * DD);
    orow[lane] = a0;
    orow[lane + 32] = a1;
}

// ---------------- aggregation: node <- mean over incident hyperedges + epilogue -
__global__ void node_agg_k(const float* __restrict__ bias,
                           const float* __restrict__ prelu_a,
                           const float* __restrict__ residual,
                           float* __restrict__ out_ext,
                           int layer2) {
    int gw = (blockIdx.x * blockDim.x + threadIdx.x) >> 5;
    int lane = threadIdx.x & 31;
    if (gw >= NN) return;
    int lo = g_node_ptr[gw], hi = g_node_ptr[gw + 1];
    float4 a0 = make_float4(0.f, 0.f, 0.f, 0.f);
    float4 a1 = a0;
    for (int s = lo; s < hi; s++) {
        int h = g_node_slots[s];
        const float4* row = (const float4*)(g_edge + (size_t)h * DD);
        float4 v0 = __ldg(&row[lane]);
        float4 v1 = __ldg(&row[lane + 32]);
        a0.x += v0.x; a0.y += v0.y; a0.z += v0.z; a0.w += v0.w;
        a1.x += v1.x; a1.y += v1.y; a1.z += v1.z; a1.w += v1.w;
    }
    float inv = (hi > lo) ? 1.f / (float)(hi - lo) : 0.f;
    float a = __ldg(prelu_a);
    float4 b0 = *(const float4*)&bias[lane * 4];
    float4 b1 = *(const float4*)&bias[128 + lane * 4];

    float4 r0, r1;
    r0.x = a0.x * inv + b0.x; r0.y = a0.y * inv + b0.y;
    r0.z = a0.z * inv + b0.z; r0.w = a0.w * inv + b0.w;
    r1.x = a1.x * inv + b1.x; r1.y = a1.y * inv + b1.y;
    r1.z = a1.z * inv + b1.z; r1.w = a1.w * inv + b1.w;

    if (layer2) {
        const float4* xr = (const float4*)(residual + (size_t)gw * DD);
        float4 x0 = __ldg(&xr[lane]);
        float4 x1 = __ldg(&xr[lane + 32]);
        r0.x += x0.x; r0.y += x0.y; r0.z += x0.z; r0.w += x0.w;
        r1.x += x1.x; r1.y += x1.y; r1.z += x1.z; r1.w += x1.w;
    }

    r0.x = (r0.x >= 0.f) ? r0.x : a * r0.x;
    r0.y = (r0.y >= 0.f) ? r0.y : a * r0.y;
    r0.z = (r0.z >= 0.f) ? r0.z : a * r0.z;
    r0.w = (r0.w >= 0.f) ? r0.w : a * r0.w;
    r1.x = (r1.x >= 0.f) ? r1.x : a * r1.x;
    r1.y = (r1.y >= 0.f) ? r1.y : a * r1.y;
    r1.z = (r1.z >= 0.f) ? r1.z : a * r1.z;
    r1.w = (r1.w >= 0.f) ? r1.w : a * r1.w;

    float* out = layer2 ? out_ext : (float*)g_h1;
    float4* orow = (float4*)(out + (size_t)gw * DD);
    orow[lane] = r0;
    orow[lane + 32] = r1;
}

// ---------------- launch ---------------------------------------------------------
extern "C" void kernel_launch(void* const* d_in, const int* in_sizes, int n_in,
                              void* d_out, int out_size) {
    const float* x   = (const float*)d_in[0];
    const float* W1  = (const float*)d_in[1];
    const float* b1  = (const float*)d_in[2];
    const float* W2  = (const float*)d_in[3];
    const float* b2  = (const float*)d_in[4];
    const float* pa  = (const float*)d_in[5];
    const void*  hei = d_in[6];
    float* out = (float*)d_out;

    // CSR build (recomputed every launch; deterministic function of inputs)
    init_k<<<(NN + 255) / 256, 256>>>();
    detect_k<<<1, 1024>>>((const unsigned long long*)hei);
    hist_k<<<(EE + 255) / 256, 256>>>(hei);
    scan_k<<<1, 1024>>>(0);                // deg_e -> he_ptr
    scan_k<<<1, 1024>>>(1);                // deg_n -> node_ptr
    cursor_k<<<(NN + 255) / 256, 256>>>();
    fill_k<<<(EE + 255) / 256, 256>>>(hei);

    dim3 gg((NN + 127) / 128, DD / 128);
    int agg_blocks = (NN * 32 + 255) / 256;   // one warp per row, 8 warps/block

    // layer 1: xw = x @ W1^T ; edge agg ; node agg (+b1, prelu) -> g_h1
    gemm_k<<<gg, 256>>>(x, W1, 0);
    edge_agg_k<<<agg_blocks, 256>>>();
    node_agg_k<<<agg_blocks, 256>>>(b1, pa, nullptr, nullptr, 0);

    // layer 2: xw = h1 @ W2^T ; edge agg ; node agg (+b2, +x residual, prelu)
    gemm_k<<<gg, 256>>>(x, W2, 1);
    edge_agg_k<<<agg_blocks, 256>>>();
    node_agg_k<<<agg_blocks, 256>>>(b2, pa, x, out, 1);
}